// round 17
// baseline (speedup 1.0000x reference)
#include <cuda_runtime.h>
#include <cuda_fp16.h>
#include <cstdint>

// ---------------- problem constants ----------------
#define B_   4
#define L_   4096
#define D_   1024
#define H_   16
#define BS_  64
#define HD_  64
#define NB_  64
#define TD_  3072           // 3*D
#define M_   (B_*L_)        // 16384
#define SCALE_ 0.125f       // HD^-0.5
#define TEMP_  0.7f

typedef __half f16;

// ---------------- device scratch (allocation-free) ----------------
__device__ f16   g_qkv16[B_*L_*TD_];            // fp16 qkv
__device__ float g_qrepr[B_*H_*NB_*HD_];
__device__ float g_krepr[B_*H_*NB_*HD_];
__device__ f16   g_phi  [B_*H_*NB_*NB_];        // P hi (fp16)
__device__ f16   g_plo  [B_*H_*NB_*NB_];        // P lo (fp16 residual)
__device__ f16   g_ks16 [B_*H_*NB_*BS_*HD_];    // sorted K fp16
__device__ f16   g_vs16 [B_*H_*NB_*BS_*HD_];    // sorted V fp16
__device__ f16   g_xh   [M_*D_];                // x fp16
__device__ f16   g_w1h  [TD_*D_];               // W_qkv^T fp16
__device__ f16   g_w2h  [D_*D_];                // W_out^T fp16
__device__ f16   g_ath  [M_*D_];                // attn out fp16

// ---------------- PTX helpers ----------------
__device__ __forceinline__ unsigned smem_u32(const void* p) {
    return (unsigned)__cvta_generic_to_shared(p);
}
__device__ __forceinline__ void ldsm4(unsigned* r, unsigned addr) {
    asm volatile("ldmatrix.sync.aligned.m8n8.x4.shared.b16 {%0,%1,%2,%3}, [%4];\n"
                 : "=r"(r[0]), "=r"(r[1]), "=r"(r[2]), "=r"(r[3]) : "r"(addr));
}
__device__ __forceinline__ void ldsm4t(unsigned* r, unsigned addr) {
    asm volatile("ldmatrix.sync.aligned.m8n8.x4.trans.shared.b16 {%0,%1,%2,%3}, [%4];\n"
                 : "=r"(r[0]), "=r"(r[1]), "=r"(r[2]), "=r"(r[3]) : "r"(addr));
}
__device__ __forceinline__ void mma16816h(float* c, const unsigned* a, const unsigned* b) {
    asm volatile(
        "mma.sync.aligned.m16n8k16.row.col.f32.f16.f16.f32 "
        "{%0,%1,%2,%3}, {%4,%5,%6,%7}, {%8,%9}, {%0,%1,%2,%3};\n"
        : "+f"(c[0]), "+f"(c[1]), "+f"(c[2]), "+f"(c[3])
        : "r"(a[0]), "r"(a[1]), "r"(a[2]), "r"(a[3]), "r"(b[0]), "r"(b[1]));
}
#define CP_ASYNC16(dst, src) \
    asm volatile("cp.async.cg.shared.global [%0], [%1], 16;\n" :: "r"(dst), "l"(src))
#define CP_COMMIT() asm volatile("cp.async.commit_group;\n")
#define CP_WAIT(n)  asm volatile("cp.async.wait_group %0;\n" :: "n"(n))

// ---------------- single-fp16 GEMM: 128x128 tile, 512 thr, warp tile 32x32 ----------------
// 16 warps/CTA (4x4), 2 CTAs/SM -> 32 warps/SM for latency hiding.
#define TSTRIDE 40
#define SA_H    0
#define SB_H    (128 * TSTRIDE)
#define STG_E   (SB_H + 128 * TSTRIDE)     // 10240 elems / stage
#define NSTG    3
#define GEMM_SMEM (NSTG * STG_E * 2)       // 61440 bytes

__global__ __launch_bounds__(512, 2) void hgemm1_kernel(
    const f16* __restrict__ A, const f16* __restrict__ Bt,
    const float* __restrict__ bias, float* __restrict__ C,
    f16* __restrict__ C16,
    float* __restrict__ QR, float* __restrict__ KR,
    int M, int N, int K)
{
    extern __shared__ f16 sm[];
    const uint32_t smb = smem_u32(sm);
    const int tid = threadIdx.x;
    const int lane = tid & 31, wid = tid >> 5;
    const int wm = wid & 3, wn = wid >> 2;       // 4x4 warp grid, warp tile 32x32
    const int quad = lane >> 3, qr = lane & 7;

    const int aRow0 = blockIdx.y * 128;
    const int bRow0 = blockIdx.x * 128;
    const int nchunks = K >> 5;

    // loader: 256 rows x 4 chunks = 1024 x 16B per stage, 2 per thread
    auto prefetch = [&](int stg, int k0) {
#pragma unroll
        for (int it = 0; it < 2; it++) {
            int c = tid + it * 512;
            int row = c >> 2;                // 0..255
            int ch  = c & 3;
            const f16* gsrc;
            unsigned soff;
            if (row < 128) {
                gsrc = A + (size_t)(aRow0 + row) * K + k0 + ch * 8;
                soff = SA_H + row * TSTRIDE + ch * 8;
            } else {
                int r = row - 128;
                gsrc = Bt + (size_t)(bRow0 + r) * K + k0 + ch * 8;
                soff = SB_H + r * TSTRIDE + ch * 8;
            }
            CP_ASYNC16(smb + (stg * STG_E + soff) * 2, gsrc);
        }
        CP_COMMIT();
    };

    prefetch(0, 0);
    prefetch(1, 32);

    float acc[2][4][4] = {};    // [mt][nt*2+half][4]
    int sidx = 0, pidx = 2;

    for (int ck = 0; ck < nchunks; ck++) {
        if (ck < nchunks - 1) { CP_WAIT(1); } else { CP_WAIT(0); }
        __syncthreads();

        if (ck + 2 < nchunks) {
            prefetch(pidx, (ck + 2) << 5);
            pidx = (pidx == 2) ? 0 : pidx + 1;
        }

        const f16* st = sm + sidx * STG_E;
        sidx = (sidx == 2) ? 0 : sidx + 1;
#pragma unroll
        for (int kk = 0; kk < 32; kk += 16) {
            unsigned af[2][4];
#pragma unroll
            for (int mt = 0; mt < 2; mt++) {
                int arow = wm * 32 + mt * 16 + qr + ((quad & 1) << 3);
                int acol = kk + ((quad >> 1) << 3);
                ldsm4(af[mt], smem_u32(st + SA_H + arow * TSTRIDE + acol));
            }
#pragma unroll
            for (int nt = 0; nt < 2; nt++) {
                int brow = wn * 32 + nt * 16 + qr + ((quad >> 1) << 3);
                int bcol = kk + ((quad & 1) << 3);
                unsigned bf[4];
                ldsm4(bf, smem_u32(st + SB_H + brow * TSTRIDE + bcol));
#pragma unroll
                for (int mt = 0; mt < 2; mt++) {
                    mma16816h(acc[mt][nt * 2],     af[mt], bf);
                    mma16816h(acc[mt][nt * 2 + 1], af[mt], bf + 2);
                }
            }
        }
    }

    const int gr0 = blockIdx.y * 128 + wm * 32 + (lane >> 2);
    const int gc0 = blockIdx.x * 128 + wn * 32 + (lane & 3) * 2;
    const bool do_repr = (QR != nullptr) && (blockIdx.x < 16);

#pragma unroll
    for (int p = 0; p < 4; p++) {
        float s0 = 0.f, s1 = 0.f;
        int c = gc0 + p * 8;
        float b0 = bias[c], b1 = bias[c + 1];
#pragma unroll
        for (int mt = 0; mt < 2; mt++) {
            int r = gr0 + mt * 16;
            float v00 = acc[mt][p][0] + b0, v01 = acc[mt][p][1] + b1;
            float v10 = acc[mt][p][2] + b0, v11 = acc[mt][p][3] + b1;
            if (C) {
                *(float2*)(C + (size_t)r * N + c)       = make_float2(v00, v01);
                *(float2*)(C + (size_t)(r + 8) * N + c) = make_float2(v10, v11);
            }
            if (C16) {
                *(__half2*)(C16 + (size_t)r * N + c) =
                    __half2(__float2half_rn(v00), __float2half_rn(v01));
                *(__half2*)(C16 + (size_t)(r + 8) * N + c) =
                    __half2(__float2half_rn(v10), __float2half_rn(v11));
            }
            s0 += v00 + v10;
            s1 += v01 + v11;
        }
        if (do_repr) {
            // sum over the 8 lane-rows of this warp
            s0 += __shfl_xor_sync(0xffffffffu, s0, 4);
            s0 += __shfl_xor_sync(0xffffffffu, s0, 8);
            s0 += __shfl_xor_sync(0xffffffffu, s0, 16);
            s1 += __shfl_xor_sync(0xffffffffu, s1, 4);
            s1 += __shfl_xor_sync(0xffffffffu, s1, 8);
            s1 += __shfl_xor_sync(0xffffffffu, s1, 16);
            if ((lane >> 2) == 0) {
                int which = c >> 10;                         // 0=q, 1=k
                int hh = (c & 1023) >> 6;
                int d  = c & 63;
                int gb = blockIdx.y >> 5;                    // batch
                int nb = ((blockIdx.y & 31) << 1) | (wm >> 1); // block index
                float* dst = which ? KR : QR;
                int idx = ((gb * H_ + hh) << 12) + (nb << 6) + d;
                atomicAdd(dst + idx,     s0 * 0.015625f);
                atomicAdd(dst + idx + 1, s1 * 0.015625f);
            }
        }
    }
}

// ---------------- x -> fp16 ----------------
__global__ void splitx_kernel(const float* __restrict__ src,
                              f16* __restrict__ dst, int n4)
{
    int i = blockIdx.x * blockDim.x + threadIdx.x;
    if (i >= n4) return;
    float4 v = ((const float4*)src)[i];
    __half2* dp = (__half2*)(dst + i * 4);
    dp[0] = __half2(__float2half_rn(v.x), __float2half_rn(v.y));
    dp[1] = __half2(__float2half_rn(v.z), __float2half_rn(v.w));
}

// ---------------- transpose + convert: W[K][N] -> T[N][K] fp16 ----------------
__global__ void wconv_kernel(const float* __restrict__ W,
                             f16* __restrict__ T, int Kd, int Nd)
{
    __shared__ float t[32][33];
    const int tx = threadIdx.x, ty = threadIdx.y;
    const int n0 = blockIdx.x * 32, k0 = blockIdx.y * 32;
#pragma unroll
    for (int j = 0; j < 4; j++)
        t[ty + j * 8][tx] = W[(size_t)(k0 + ty + j * 8) * Nd + n0 + tx];
    __syncthreads();
#pragma unroll
    for (int j = 0; j < 4; j++) {
        float v = t[tx][ty + j * 8];
        size_t idx = (size_t)(n0 + ty + j * 8) * Kd + k0 + tx;
        T[idx] = __float2half_rn(v);
    }
}

// ---------------- sinkhorn -> P (fp16 hi/lo), parallel logsumexp ----------------
__global__ __launch_bounds__(256) void sinkhorn_kernel(
    const float* __restrict__ qrepr, const float* __restrict__ krepr,
    const float* __restrict__ gumbel,
    f16* __restrict__ Phi, f16* __restrict__ Plo)
{
    __shared__ float La[64][65];
    const int bh = blockIdx.x;
    const int tid = threadIdx.x;
    const float* qr = qrepr + bh * NB_ * HD_;
    const float* kr = krepr + bh * NB_ * HD_;

    for (int e = tid; e < NB_ * NB_; e += 256) {
        int nn = e >> 6, m = e & 63;
        float s = 0.f;
#pragma unroll 16
        for (int d = 0; d < HD_; d++) s += qr[nn * HD_ + d] * kr[m * HD_ + d];
        La[nn][m] = (s * SCALE_ + gumbel[bh * NB_ * NB_ + e]) * (1.0f / TEMP_);
    }
    __syncthreads();

    const int rr = tid >> 2, qd = tid & 3;
    for (int it = 0; it < 7; it++) {
        {
            float mx = -1e30f;
#pragma unroll
            for (int i = 0; i < 16; i++) mx = fmaxf(mx, La[rr][qd * 16 + i]);
            mx = fmaxf(mx, __shfl_xor_sync(0xffffffffu, mx, 1));
            mx = fmaxf(mx, __shfl_xor_sync(0xffffffffu, mx, 2));
            float se = 0.f;
#pragma unroll
            for (int i = 0; i < 16; i++) se += expf(La[rr][qd * 16 + i] - mx);
            se += __shfl_xor_sync(0xffffffffu, se, 1);
            se += __shfl_xor_sync(0xffffffffu, se, 2);
            float ls = mx + logf(se);
#pragma unroll
            for (int i = 0; i < 16; i++) La[rr][qd * 16 + i] -= ls;
        }
        __syncthreads();
        {
            float mx = -1e30f;
#pragma unroll
            for (int i = 0; i < 16; i++) mx = fmaxf(mx, La[qd * 16 + i][rr]);
            mx = fmaxf(mx, __shfl_xor_sync(0xffffffffu, mx, 1));
            mx = fmaxf(mx, __shfl_xor_sync(0xffffffffu, mx, 2));
            float se = 0.f;
#pragma unroll
            for (int i = 0; i < 16; i++) se += expf(La[qd * 16 + i][rr] - mx);
            se += __shfl_xor_sync(0xffffffffu, se, 1);
            se += __shfl_xor_sync(0xffffffffu, se, 2);
            float ls = mx + logf(se);
#pragma unroll
            for (int i = 0; i < 16; i++) La[qd * 16 + i][rr] -= ls;
        }
        __syncthreads();
    }
    for (int e = tid; e < NB_ * NB_; e += 256) {
        float p = expf(La[e >> 6][e & 63]);
        f16 hp = __float2half_rn(p);
        Phi[bh * 4096 + e] = hp;
        Plo[bh * 4096 + e] = __float2half_rn(p - __half2float(hp));
    }
}

// ---------------- tensor-core k/v soft permutation ----------------
#define PP_STR 72
#define XX_STR 264
#define SO_PHI 0
#define SO_PLO 9216
#define SO_X   18432
#define SORT_SMEM (SO_X + 64 * XX_STR * 2)   // 52224 bytes

__global__ __launch_bounds__(256, 2) void sortp_kernel(
    const f16* __restrict__ qkv16, const f16* __restrict__ Phi,
    const f16* __restrict__ Plo,
    f16* __restrict__ ks16, f16* __restrict__ vs16)
{
    extern __shared__ __align__(16) char smc[];
    const uint32_t smb = smem_u32(smc);
    f16* SPH = (f16*)(smc + SO_PHI);
    f16* SPL = (f16*)(smc + SO_PLO);
    f16* SX  = (f16*)(smc + SO_X);

    const int bh = blockIdx.x;
    const int fc = blockIdx.y;
    const int which = blockIdx.z;
    const int b = bh >> 4, h = bh & 15;
    const int tid = threadIdx.x;
    const int lane = tid & 31, wid = tid >> 5;
    const int quad = lane >> 3, qr = lane & 7;

    const f16* pg_hi = Phi + (size_t)bh * 4096;
    const f16* pg_lo = Plo + (size_t)bh * 4096;
    const f16* xbase = qkv16 + (size_t)b * L_ * TD_ + (which ? 2 * D_ : D_) + h * HD_;

#pragma unroll
    for (int it = 0; it < 12; it++) {
        int c = tid + it * 256;
        if (c < 512) {
            int row = c >> 3, ch = c & 7;
            CP_ASYNC16(smb + SO_PHI + row * 144 + ch * 16, pg_hi + row * 64 + ch * 8);
        } else if (c < 1024) {
            int cc = c - 512;
            int row = cc >> 3, ch = cc & 7;
            CP_ASYNC16(smb + SO_PLO + row * 144 + ch * 16, pg_lo + row * 64 + ch * 8);
        } else {
            int cx = c - 1024;
            int m = cx >> 5;
            int sidx = (cx >> 3) & 3;
            int ch = cx & 7;
            const f16* src = xbase + (size_t)(m * 64 + fc * 4 + sidx) * TD_ + ch * 8;
            CP_ASYNC16(smb + SO_X + m * (XX_STR * 2) + sidx * 128 + ch * 16, src);
        }
    }
    CP_COMMIT(); CP_WAIT(0);
    __syncthreads();

    const int mt = wid & 3, nh = wid >> 2;
    float acc[8][2][4] = {};
#pragma unroll
    for (int k16 = 0; k16 < 4; k16++) {
        unsigned aoff = (mt * 16 + qr + ((quad & 1) << 3)) * PP_STR
                        + k16 * 16 + ((quad >> 1) << 3);
        unsigned aH[4], aL[4];
        ldsm4(aH, smem_u32(SPH + aoff));
        ldsm4(aL, smem_u32(SPL + aoff));
#pragma unroll
        for (int nt = 0; nt < 8; nt++) {
            unsigned voff = (k16 * 16 + qr + ((quad & 1) << 3)) * XX_STR
                            + nh * 128 + nt * 16 + ((quad >> 1) << 3);
            unsigned xF[4];
            ldsm4t(xF, smem_u32(SX + voff));
            mma16816h(acc[nt][0], aH, xF);
            mma16816h(acc[nt][1], aH, xF + 2);
            mma16816h(acc[nt][0], aL, xF);
            mma16816h(acc[nt][1], aL, xF + 2);
        }
    }

    f16* dstg = which ? vs16 : ks16;
    const int n2r = mt * 16 + (lane >> 2);
    const size_t obase = (size_t)bh * NB_ * 4096 + fc * 256;
#pragma unroll
    for (int nt = 0; nt < 8; nt++) {
#pragma unroll
        for (int hf = 0; hf < 2; hf++) {
            int c = nh * 128 + nt * 16 + hf * 8 + (lane & 3) * 2;
            *(__half2*)(dstg + obase + (size_t)n2r * 4096 + c) =
                __half2(__float2half_rn(acc[nt][hf][0]),
                        __float2half_rn(acc[nt][hf][1]));
            *(__half2*)(dstg + obase + (size_t)(n2r + 8) * 4096 + c) =
                __half2(__float2half_rn(acc[nt][hf][2]),
                        __float2half_rn(acc[nt][hf][3]));
        }
    }
}

// ---------------- all-fp16 attention: register softmax, 2 CTAs/SM ----------------
#define AQ_STR 72
#define AP_STR 136
#define O_SQ   0
#define O_SK   9216
#define O_SV   27648
#define O_SP   46080
#define O_EXC  63488
#define ATTN_SMEM (O_EXC + 2 * 64 * 8)     // 64512 bytes

__global__ __launch_bounds__(256, 2) void attn_kernel(
    const f16* __restrict__ qkv16, const f16* __restrict__ ks16,
    const f16* __restrict__ vs16, f16* __restrict__ ath)
{
    extern __shared__ __align__(16) char smc[];
    const uint32_t smb = smem_u32(smc);
    f16* SQ = (f16*)(smc + O_SQ);
    f16* SK = (f16*)(smc + O_SK);
    f16* SV = (f16*)(smc + O_SV);
    f16* SP = (f16*)(smc + O_SP);
    float2* EXC = (float2*)(smc + O_EXC);

    const int blk = blockIdx.x;
    const int n2 = blk & 63;
    const int h = (blk >> 6) & 15;
    const int b = blk >> 10;
    const int bh = b * H_ + h;
    const int tid = threadIdx.x;
    const int lane = tid & 31, wid = tid >> 5;
    const int quad = lane >> 3, qr = lane & 7;
    const int nn = (n2 + 1) & 63;

    const f16* qb16 = qkv16 + ((size_t)(b * L_ + n2 * BS_)) * TD_ + h * HD_;
    const f16* kn16 = ks16 + ((size_t)(bh * NB_ + nn)) * BS_ * HD_;
    const f16* vn16 = vs16 + ((size_t)(bh * NB_ + nn)) * BS_ * HD_;

#pragma unroll
    for (int it = 0; it < 6; it++) {
        int c = tid + it * 256;
        int row = c >> 3;
        int ch = c & 7;
        const f16* src;
        uint32_t dst;
        if (row < 64) {
            src = qb16 + (size_t)row * TD_ + ch * 8;
            dst = O_SQ + row * 144 + ch * 16;
        } else if (row < 128) {
            int s = row - 64;
            src = qb16 + D_ + (size_t)s * TD_ + ch * 8;
            dst = O_SK + s * 144 + ch * 16;
        } else {
            int s = row - 128;
            src = kn16 + s * 64 + ch * 8;
            dst = O_SK + (64 + s) * 144 + ch * 16;
        }
        CP_ASYNC16(smb + dst, src);
    }
    CP_COMMIT();
#pragma unroll
    for (int it = 0; it < 4; it++) {
        int c = tid + it * 256;
        int row = c >> 3;
        int ch = c & 7;
        const f16* src;
        uint32_t dst;
        if (row < 64) {
            src = qb16 + 2 * D_ + (size_t)row * TD_ + ch * 8;
            dst = O_SV + row * 144 + ch * 16;
        } else {
            int s = row - 64;
            src = vn16 + s * 64 + ch * 8;
            dst = O_SV + (64 + s) * 144 + ch * 16;
        }
        CP_ASYNC16(smb + dst, src);
    }
    CP_COMMIT();
    CP_WAIT(1);
    __syncthreads();

    const int wm = wid & 3, wn = wid >> 2;
    const int r0 = wm * 16 + (lane >> 2);

    float sacc[8][4] = {};
#pragma unroll
    for (int k16 = 0; k16 < 64; k16 += 16) {
        unsigned aoff = (wm * 16 + qr + ((quad & 1) << 3)) * AQ_STR
                        + k16 + ((quad >> 1) << 3);
        unsigned aF[4];
        ldsm4(aF, smem_u32(SQ + aoff));
#pragma unroll
        for (int nt = 0; nt < 4; nt++) {
            unsigned boff = (wn * 64 + nt * 16 + qr + ((quad >> 1) << 3)) * AQ_STR
                            + k16 + ((quad & 1) << 3);
            unsigned bF[4];
            ldsm4(bF, smem_u32(SK + boff));
            mma16816h(sacc[nt * 2],     aF, bF);
            mma16816h(sacc[nt * 2 + 1], aF, bF + 2);
        }
    }
    {
        const bool maskme = (n2 == NB_ - 1) && (wn == 1);
#pragma unroll
        for (int p = 0; p < 8; p++)
#pragma unroll
            for (int q = 0; q < 4; q++)
                sacc[p][q] = maskme ? -1e9f : sacc[p][q] * SCALE_;
    }

    {
        float m0 = -1e30f, m1 = -1e30f;
#pragma unroll
        for (int p = 0; p < 8; p++) {
            m0 = fmaxf(m0, fmaxf(sacc[p][0], sacc[p][1]));
            m1 = fmaxf(m1, fmaxf(sacc[p][2], sacc[p][3]));
        }
        m0 = fmaxf(m0, __shfl_xor_sync(0xffffffffu, m0, 1));
        m0 = fmaxf(m0, __shfl_xor_sync(0xffffffffu, m0, 2));
        m1 = fmaxf(m1, __shfl_xor_sync(0xffffffffu, m1, 1));
        m1 = fmaxf(m1, __shfl_xor_sync(0xffffffffu, m1, 2));
        float s0 = 0.f, s1 = 0.f;
#pragma unroll
        for (int p = 0; p < 8; p++) {
            s0 += __expf(sacc[p][0] - m0) + __expf(sacc[p][1] - m0);
            s1 += __expf(sacc[p][2] - m1) + __expf(sacc[p][3] - m1);
        }
        s0 += __shfl_xor_sync(0xffffffffu, s0, 1);
        s0 += __shfl_xor_sync(0xffffffffu, s0, 2);
        s1 += __shfl_xor_sync(0xffffffffu, s1, 1);
        s1 += __shfl_xor_sync(0xffffffffu, s1, 2);
        if ((lane & 3) == 0) {
            EXC[wn * 64 + r0]     = make_float2(m0, s0);
            EXC[wn * 64 + r0 + 8] = make_float2(m1, s1);
        }
    }
    __syncthreads();

    {
        float2 a0 = EXC[r0],      b0 = EXC[64 + r0];
        float2 a1 = EXC[r0 + 8],  b1 = EXC[64 + r0 + 8];
        float g0 = fmaxf(a0.x, b0.x);
        float inv0 = 1.0f / (a0.y * __expf(a0.x - g0) + b0.y * __expf(b0.x - g0));
        float g1 = fmaxf(a1.x, b1.x);
        float inv1 = 1.0f / (a1.y * __expf(a1.x - g1) + b1.y * __expf(b1.x - g1));
#pragma unroll
        for (int p = 0; p < 8; p++) {
            int j0 = wn * 64 + (p >> 1) * 16 + (p & 1) * 8 + (lane & 3) * 2;
            *(__half2*)(SP + r0 * AP_STR + j0) =
                __half2(__float2half_rn(__expf(sacc[p][0] - g0) * inv0),
                        __float2half_rn(__expf(sacc[p][1] - g0) * inv0));
            *(__half2*)(SP + (r0 + 8) * AP_STR + j0) =
                __half2(__float2half_rn(__expf(sacc[p][2] - g1) * inv1),
                        __float2half_rn(__expf(sacc[p][3] - g1) * inv1));
        }
    }
    CP_WAIT(0);
    __syncthreads();

    {
        float oacc[4][4] = {};
#pragma unroll
        for (int k16 = 0; k16 < 128; k16 += 16) {
            unsigned poff = (wm * 16 + qr + ((quad & 1) << 3)) * AP_STR
                            + k16 + ((quad >> 1) << 3);
            unsigned pF[4];
            ldsm4(pF, smem_u32(SP + poff));
#pragma unroll
            for (int nt = 0; nt < 2; nt++) {
                unsigned voff = (k16 + qr + ((quad & 1) << 3)) * AQ_STR
                                + wn * 32 + nt * 16 + ((quad >> 1) << 3);
                unsigned vF[4];
                ldsm4t(vF, smem_u32(SV + voff));
                mma16816h(oacc[nt * 2],     pF, vF);
                mma16816h(oacc[nt * 2 + 1], pF, vF + 2);
            }
        }
        const size_t obase = ((size_t)(b * L_ + n2 * BS_)) * D_ + h * HD_;
#pragma unroll
        for (int p = 0; p < 4; p++) {
            int d0 = wn * 32 + (p >> 1) * 16 + (p & 1) * 8 + (lane & 3) * 2;
#pragma unroll
            for (int rr = 0; rr < 2; rr++) {
                float v0 = oacc[p][rr * 2], v1 = oacc[p][rr * 2 + 1];
                size_t o = obase + (size_t)(r0 + rr * 8) * D_ + d0;
                *(__half2*)(ath + o) =
                    __half2(__float2half_rn(v0), __float2half_rn(v1));
            }
        }
    }
}

// ---------------- launch ----------------
extern "C" void kernel_launch(void* const* d_in, const int* in_sizes, int n_in,
                              void* d_out, int out_size)
{
    const float* x      = (const float*)d_in[0];
    const float* gumbel = (const float*)d_in[1];
    const float* W_qkv  = (const float*)d_in[2];
    const float* b_qkv  = (const float*)d_in[3];
    const float* W_out  = (const float*)d_in[4];
    const float* b_out  = (const float*)d_in[5];
    float* out = (float*)d_out;

    float *qr, *kr;
    f16 *qkv16, *phi, *plo, *ks16, *vs16, *xh, *w1h, *w2h, *ath;
    cudaGetSymbolAddress((void**)&qkv16, g_qkv16);
    cudaGetSymbolAddress((void**)&qr,  g_qrepr);
    cudaGetSymbolAddress((void**)&kr,  g_krepr);
    cudaGetSymbolAddress((void**)&phi, g_phi);
    cudaGetSymbolAddress((void**)&plo, g_plo);
    cudaGetSymbolAddress((void**)&ks16, g_ks16);
    cudaGetSymbolAddress((void**)&vs16, g_vs16);
    cudaGetSymbolAddress((void**)&xh,  g_xh);
    cudaGetSymbolAddress((void**)&w1h, g_w1h);
    cudaGetSymbolAddress((void**)&w2h, g_w2h);
    cudaGetSymbolAddress((void**)&ath, g_ath);

    cudaFuncSetAttribute(attn_kernel,
                         cudaFuncAttributeMaxDynamicSharedMemorySize, ATTN_SMEM);
    cudaFuncSetAttribute(hgemm1_kernel,
                         cudaFuncAttributeMaxDynamicSharedMemorySize, GEMM_SMEM);
    cudaFuncSetAttribute(sortp_kernel,
                         cudaFuncAttributeMaxDynamicSharedMemorySize, SORT_SMEM);

    // conversions
    splitx_kernel<<<(M_ * D_ / 4 + 255) / 256, 256>>>(x, xh, M_ * D_ / 4);
    wconv_kernel<<<dim3(TD_ / 32, D_ / 32), dim3(32, 8)>>>(W_qkv, w1h, D_, TD_);
    wconv_kernel<<<dim3(D_ / 32, D_ / 32), dim3(32, 8)>>>(W_out, w2h, D_, D_);

    cudaMemsetAsync(qr, 0, B_ * H_ * NB_ * HD_ * sizeof(float));
    cudaMemsetAsync(kr, 0, B_ * H_ * NB_ * HD_ * sizeof(float));

    // 1) qkv = x @ W_qkv + b_qkv  (fp16 out + fused repr sums)
    hgemm1_kernel<<<dim3(TD_ / 128, M_ / 128), 512, GEMM_SMEM>>>(
        xh, w1h, b_qkv, (float*)nullptr, qkv16, qr, kr, M_, TD_, D_);

    // 2) sinkhorn -> P (fp16 hi/lo)
    sinkhorn_kernel<<<B_ * H_, 256>>>(qr, kr, gumbel, phi, plo);

    // 3) tensor-core soft permutation of K/V blocks
    sortp_kernel<<<dim3(B_ * H_, 16, 2), 256, SORT_SMEM>>>(
        qkv16, phi, plo, ks16, vs16);

    // 4) attention (register softmax)
    attn_kernel<<<B_ * H_ * NB_, 256, ATTN_SMEM>>>(qkv16, ks16, vs16, ath);

    // 5) out = attn @ W_out + b_out
    hgemm1_kernel<<<dim3(D_ / 128, M_ / 128), 512, GEMM_SMEM>>>(
        ath, w2h, b_out, out, (f16*)nullptr, (float*)nullptr, (float*)nullptr,
        M_, D_, D_);
}